// round 10
// baseline (speedup 1.0000x reference)
#include <cuda_runtime.h>
#include <cuda_fp16.h>
#include <math.h>

#define NN 50000
#define EE 800000
#define F1 128
#define HEADS 8
#define HID 16
#define OUTC 16
#define NEG_SLOPE 0.2f
#define MAXDEG 64

typedef unsigned long long ull;

// packed f32x2 helpers (sm_103a)
__device__ __forceinline__ ull pack2(float lo, float hi) {
    ull r;
    asm("mov.b64 %0, {%1, %2};" : "=l"(r) : "f"(lo), "f"(hi));
    return r;
}
__device__ __forceinline__ void unpack2(ull v, float& lo, float& hi) {
    asm("mov.b64 {%0, %1}, %2;" : "=f"(lo), "=f"(hi) : "l"(v));
}
__device__ __forceinline__ ull fma2(ull a, ull b, ull c) {
    ull d;
    asm("fma.rn.f32x2 %0, %1, %2, %3;" : "=l"(d) : "l"(a), "l"(b), "l"(c));
    return d;
}

// ---------------- scratch ----------------
__device__ __align__(16) __half g_h1h[NN * F1];
__device__ __align__(16) float  g_out1[NN * F1];
__device__ float g_als1[NN * HEADS];
__device__ float g_ald1[NN * HEADS];
__device__ __align__(16) __half g_h2h[NN * OUTC];
__device__ float g_als2[NN];
__device__ float g_ald2[NN];
__device__ int   g_cnt[NN];
__device__ int   g_csr[NN * MAXDEG];

// ---------------- bucket init: self loop in slot 0 ----------------
__global__ void k_zero() {
    int i = blockIdx.x * blockDim.x + threadIdx.x;
    if (i < NN) {
        g_cnt[i] = 1;
        g_csr[i * MAXDEG] = i;
    }
}

__global__ void k_fill(const int* __restrict__ ei) {
    int base = (blockIdx.x * blockDim.x + threadIdx.x) * 4;
    if (base >= EE) return;
#pragma unroll
    for (int k = 0; k < 4; k++) {
        int e = base + k;
        if (e < EE) {
            int s = ei[e], d = ei[EE + e];
            int pos = atomicAdd(&g_cnt[d], 1);
            if (pos < MAXDEG) g_csr[d * MAXDEG + pos] = s;
        }
    }
}

// ---------------- layer 1: GEMM with packed f32x2 FMA ----------------
// 8 nodes/block; smem transposed xs_t[k][j]; thread t owns output col t.
__global__ void k_gemm1(const float* __restrict__ x, const float* __restrict__ W1,
                        const float* __restrict__ as1, const float* __restrict__ ad1) {
    int nb = blockIdx.x * 8;
    int t = threadIdx.x;                 // 128
    __shared__ __align__(16) float xs_t[F1][8];   // [k][node] 4KB
    {
        int j = t & 7;
        int k4 = t >> 3;                 // 0..15
        const float* row = x + (nb + j) * F1;
#pragma unroll
        for (int half = 0; half < 2; half++) {
            int kk = (k4 + half * 16) * 4;
            float4 v = *(const float4*)(row + kk);
            xs_t[kk + 0][j] = v.x;
            xs_t[kk + 1][j] = v.y;
            xs_t[kk + 2][j] = v.z;
            xs_t[kk + 3][j] = v.w;
        }
    }
    __syncthreads();
    ull acc2[4] = {0, 0, 0, 0};          // node pairs (0,1)(2,3)(4,5)(6,7)
#pragma unroll 8
    for (int k = 0; k < F1; k++) {
        float w = W1[k * F1 + t];
        ull wp = pack2(w, w);
        const longlong2* xr = (const longlong2*)&xs_t[k][0];
        longlong2 p0 = xr[0];            // nodes 0,1 | 2,3
        longlong2 p1 = xr[1];            // nodes 4,5 | 6,7
        acc2[0] = fma2((ull)p0.x, wp, acc2[0]);
        acc2[1] = fma2((ull)p0.y, wp, acc2[1]);
        acc2[2] = fma2((ull)p1.x, wp, acc2[2]);
        acc2[3] = fma2((ull)p1.y, wp, acc2[3]);
    }
    float acc[8];
#pragma unroll
    for (int p = 0; p < 4; p++) unpack2(acc2[p], acc[2 * p], acc[2 * p + 1]);
    float as = as1[t], ad = ad1[t];
#pragma unroll
    for (int j = 0; j < 8; j++) {
        g_h1h[(nb + j) * F1 + t] = __float2half(acc[j]);
        float p = acc[j] * as, q = acc[j] * ad;
#pragma unroll
        for (int off = 8; off >= 1; off >>= 1) {
            p += __shfl_down_sync(0xffffffffu, p, off, 16);
            q += __shfl_down_sync(0xffffffffu, q, off, 16);
        }
        if ((t & 15) == 0) {
            g_als1[(nb + j) * HEADS + (t >> 4)] = p;
            g_ald1[(nb + j) * HEADS + (t >> 4)] = q;
        }
    }
}

// ---------------- layer 1: aggregation, warp/node, phase-weights + f32x2 ----------------
// lane l: channels [4l,4l+4), head h=l>>2. Phase: lane = edge(l>>3)*8 + head(l&7).
__global__ void k_agg1(const float* __restrict__ b1) {
    int warp = threadIdx.x >> 5;
    int lane = threadIdx.x & 31;
    int d = blockIdx.x * 8 + warp;
    if (d >= NN) return;
    int h = lane >> 2;
    int cnt = g_cnt[d];
    const int* bucket = g_csr + d * MAXDEG;
    float ald_ph = g_ald1[d * HEADS + (lane & 7)];   // for phase (head = lane&7)
    ull acc01 = 0, acc23 = 0;
    float den = 0.f;
    for (int i0 = 0; i0 < cnt; i0 += 4) {
        // phase: compute w for 4 edges x 8 heads
        int e_idx = i0 + (lane >> 3);
        int s_ph = bucket[(e_idx < cnt) ? e_idx : 0];
        float al = g_als1[s_ph * HEADS + (lane & 7)] + ald_ph;
        al = fmaxf(al, NEG_SLOPE * al);
        float w_ph = (e_idx < cnt) ? __expf(al) : 0.f;
        int lim = min(4, cnt - i0);
#pragma unroll 4
        for (int j = 0; j < 4; j++) {
            if (j >= lim) break;
            float wj = __shfl_sync(0xffffffffu, w_ph, j * 8 + h);
            int   sj = __shfl_sync(0xffffffffu, s_ph, j * 8);
            den += wj;
            ull wp = pack2(wj, wj);
            uint2 hv = *(const uint2*)(g_h1h + sj * F1 + lane * 4);
            float2 f0 = __half22float2(*(const __half2*)&hv.x);
            float2 f1 = __half22float2(*(const __half2*)&hv.y);
            acc01 = fma2(pack2(f0.x, f0.y), wp, acc01);
            acc23 = fma2(pack2(f1.x, f1.y), wp, acc23);
        }
    }
    float a0, a1, a2, a3;
    unpack2(acc01, a0, a1);
    unpack2(acc23, a2, a3);
    float inv = 1.f / den;
    float4 bv = *(const float4*)(b1 + lane * 4);
    float4 o;
    o.x = a0 * inv + bv.x;
    o.y = a1 * inv + bv.y;
    o.z = a2 * inv + bv.z;
    o.w = a3 * inv + bv.w;
    o.x = o.x > 0.f ? o.x : expm1f(o.x);
    o.y = o.y > 0.f ? o.y : expm1f(o.y);
    o.z = o.z > 0.f ? o.z : expm1f(o.z);
    o.w = o.w > 0.f ? o.w : expm1f(o.w);
    *(float4*)(g_out1 + d * F1 + lane * 4) = o;
}

// ---------------- layer 2: GEMM, 16 rows/block, smem-staged rows ----------------
__global__ void k_gemm2(const float* __restrict__ W2,
                        const float* __restrict__ as2, const float* __restrict__ ad2) {
    int t = threadIdx.x;
    int rbase = blockIdx.x * 16;
    __shared__ float4 sh[16][32];
    __shared__ float ws[F1][OUTC];
    const float4* src = (const float4*)(g_out1 + rbase * F1);
    ((float4*)sh)[t]       = src[t];
    ((float4*)sh)[t + 256] = src[t + 256];
#pragma unroll
    for (int i = t; i < F1 * OUTC; i += 256) ws[i >> 4][i & 15] = W2[i];
    __syncthreads();
    int r_loc = t >> 4, c = t & 15;
    float acc = 0.f;
#pragma unroll 8
    for (int k4 = 0; k4 < 32; k4++) {
        float4 hv = sh[r_loc][k4];
        acc = fmaf(hv.x, ws[k4 * 4 + 0][c], acc);
        acc = fmaf(hv.y, ws[k4 * 4 + 1][c], acc);
        acc = fmaf(hv.z, ws[k4 * 4 + 2][c], acc);
        acc = fmaf(hv.w, ws[k4 * 4 + 3][c], acc);
    }
    int r = rbase + r_loc;
    g_h2h[r * OUTC + c] = __float2half(acc);
    float p = acc * as2[c], q = acc * ad2[c];
#pragma unroll
    for (int off = 8; off >= 1; off >>= 1) {
        p += __shfl_down_sync(0xffffffffu, p, off, 16);
        q += __shfl_down_sync(0xffffffffu, q, off, 16);
    }
    if (c == 0) { g_als2[r] = p; g_ald2[r] = q; }
}

// ---------------- layer 2: aggregation, 16-lane group per dst node, phase-weights ----------------
__global__ void k_agg2(const float* __restrict__ b2, float* __restrict__ out) {
    int t = threadIdx.x;
    int d = blockIdx.x * 16 + (t >> 4);
    if (d >= NN) return;
    int c = t & 15;
    unsigned hm = 0xFFFFu << (t & 16);
    int cnt = g_cnt[d];
    const int* bucket = g_csr + d * MAXDEG;
    float ald = g_ald2[d];
    float acc = 0.f, den = 0.f;
    for (int i0 = 0; i0 < cnt; i0 += 16) {
        int i = i0 + c;
        int s = bucket[(i < cnt) ? i : 0];
        float al = g_als2[s] + ald;
        al = fmaxf(al, NEG_SLOPE * al);
        float w = (i < cnt) ? __expf(al) : 0.f;
        int lim = min(16, cnt - i0);
#pragma unroll 8
        for (int j = 0; j < lim; j++) {
            int   sj = __shfl_sync(hm, s, j, 16);
            float wj = __shfl_sync(hm, w, j, 16);
            den += wj;
            acc = fmaf(wj, __half2float(g_h2h[sj * OUTC + c]), acc);
        }
    }
    out[d * OUTC + c] = acc / den + b2[c];
}

// ---------------- launch ----------------
extern "C" void kernel_launch(void* const* d_in, const int* in_sizes, int n_in,
                              void* d_out, int out_size) {
    const float* x   = (const float*)d_in[0];
    const int*   ei  = (const int*)d_in[1];
    const float* W1  = (const float*)d_in[2];
    const float* as1 = (const float*)d_in[3];
    const float* ad1 = (const float*)d_in[4];
    const float* b1  = (const float*)d_in[5];
    const float* W2  = (const float*)d_in[6];
    const float* as2 = (const float*)d_in[7];
    const float* ad2 = (const float*)d_in[8];
    const float* b2  = (const float*)d_in[9];
    float* out = (float*)d_out;

    k_zero<<<(NN + 255) / 256, 256>>>();
    k_fill<<<(EE / 4 + 255) / 256, 256>>>(ei);
    k_gemm1<<<NN / 8, 128>>>(x, W1, as1, ad1);
    k_agg1<<<(NN + 7) / 8, 256>>>(b1);
    k_gemm2<<<(NN + 15) / 16, 256>>>(W2, as2, ad2);
    k_agg2<<<(NN + 15) / 16, 256>>>(b2, out);
}

// round 11
// speedup vs baseline: 1.1661x; 1.1661x over previous
#include <cuda_runtime.h>
#include <cuda_fp16.h>
#include <mma.h>
#include <math.h>

using namespace nvcuda;

#define NN 50000
#define EE 800000
#define F1 128
#define HEADS 8
#define HID 16
#define OUTC 16
#define NEG_SLOPE 0.2f
#define MAXDEG 64

// ---------------- scratch ----------------
__device__ __align__(16) __half g_h1h[NN * F1];
__device__ __align__(16) float  g_out1[NN * F1];
__device__ float g_als1[NN * HEADS];
__device__ float g_ald1[NN * HEADS];
__device__ __align__(16) __half g_h2h[NN * OUTC];
__device__ float g_als2[NN];
__device__ float g_ald2[NN];
__device__ int   g_cnt[NN];
__device__ int   g_csr[NN * MAXDEG];
__device__ __align__(16) __half g_W1h[F1 * F1];

// ---------------- bucket init: self loop in slot 0 ----------------
__global__ void k_zero() {
    int i = blockIdx.x * blockDim.x + threadIdx.x;
    if (i < NN) {
        g_cnt[i] = 1;
        g_csr[i * MAXDEG] = i;
    }
}

__global__ void k_fill(const int* __restrict__ ei) {
    int base = (blockIdx.x * blockDim.x + threadIdx.x) * 4;
    if (base >= EE) return;
#pragma unroll
    for (int k = 0; k < 4; k++) {
        int e = base + k;
        if (e < EE) {
            int s = ei[e], d = ei[EE + e];
            int pos = atomicAdd(&g_cnt[d], 1);
            if (pos < MAXDEG) g_csr[d * MAXDEG + pos] = s;
        }
    }
}

// ---------------- W1 -> half ----------------
__global__ void k_convW(const float* __restrict__ W1) {
    int i = blockIdx.x * blockDim.x + threadIdx.x;
    if (i < F1 * F1) g_W1h[i] = __float2half(W1[i]);
}

// ---------------- layer 1: wmma GEMM (32 rows/block) + fused logits ----------------
__global__ void __launch_bounds__(256) k_gemm1(const float* __restrict__ x,
                                               const float* __restrict__ as1,
                                               const float* __restrict__ ad1) {
    __shared__ __align__(32) __half Bs[F1 * F1];          // 32KB, W1 row-major [k][n]
    __shared__ __align__(32) unsigned char ACbuf[32 * F1 * 4]; // 16KB: A(half,8KB) then C(float,16KB)
    __half* As = (__half*)ACbuf;                          // 32 x 128 row-major
    float*  Cs = (float*)ACbuf;                           // 32 x 128 row-major (after mma)

    int t = threadIdx.x;
    int rows = blockIdx.x * 32;

    // stage A: 4096 elems, 16 per thread (4 float4), convert fp32 -> half, zero-pad OOB rows
#pragma unroll
    for (int i = 0; i < 4; i++) {
        int idx = t + 256 * i;            // float4 index within tile
        int le  = idx * 4;                // linear element
        int r   = le >> 7;
        float4 f = {0.f, 0.f, 0.f, 0.f};
        if (rows + r < NN) f = ((const float4*)x)[rows * 32 + idx];
        ((__half2*)As)[idx * 2 + 0] = __floats2half2_rn(f.x, f.y);
        ((__half2*)As)[idx * 2 + 1] = __floats2half2_rn(f.z, f.w);
    }
    // stage B: 16384 half = 2048 int4, 8 per thread
#pragma unroll
    for (int i = 0; i < 8; i++) {
        int idx = t + 256 * i;
        ((int4*)Bs)[idx] = ((const int4*)g_W1h)[idx];
    }
    __syncthreads();

    // mma: 8 warps; warp w owns output cols [16w,16w+16), rows 0-15 and 16-31
    int w = t >> 5;
    wmma::fragment<wmma::accumulator, 16, 16, 16, float> c0, c1;
    wmma::fill_fragment(c0, 0.f);
    wmma::fill_fragment(c1, 0.f);
#pragma unroll
    for (int k = 0; k < 8; k++) {
        wmma::fragment<wmma::matrix_a, 16, 16, 16, __half, wmma::row_major> a0, a1;
        wmma::fragment<wmma::matrix_b, 16, 16, 16, __half, wmma::row_major> b;
        wmma::load_matrix_sync(a0, As + 0 * 16 * F1 + k * 16, F1);
        wmma::load_matrix_sync(a1, As + 1 * 16 * F1 + k * 16, F1);
        wmma::load_matrix_sync(b, Bs + (k * 16) * F1 + w * 16, F1);
        wmma::mma_sync(c0, a0, b, c0);
        wmma::mma_sync(c1, a1, b, c1);
    }
    __syncthreads();                      // all A reads done before C overwrites
    wmma::store_matrix_sync(Cs + 0 * 16 * F1 + w * 16, c0, F1, wmma::mem_row_major);
    wmma::store_matrix_sync(Cs + 1 * 16 * F1 + w * 16, c1, F1, wmma::mem_row_major);
    __syncthreads();

    // epilogue: h1h store + per-head logits
    int col = t & 127;
    int rhalf = t >> 7;                   // 0 or 1
    float as = as1[col], ad = ad1[col];
#pragma unroll
    for (int r = 0; r < 16; r++) {
        int row = r * 2 + rhalf;
        int grow = rows + row;
        float val = Cs[row * F1 + col];
        float p = val * as, q = val * ad;
#pragma unroll
        for (int off = 8; off >= 1; off >>= 1) {
            p += __shfl_down_sync(0xffffffffu, p, off, 16);
            q += __shfl_down_sync(0xffffffffu, q, off, 16);
        }
        if (grow < NN) {
            g_h1h[grow * F1 + col] = __float2half(val);
            if ((col & 15) == 0) {
                g_als1[grow * HEADS + (col >> 4)] = p;
                g_ald1[grow * HEADS + (col >> 4)] = q;
            }
        }
    }
}

// ---------------- layer 1: aggregation, one WARP per dst node (R8 shape) ----------------
__global__ void k_agg1(const float* __restrict__ b1) {
    int warp = threadIdx.x >> 5;
    int lane = threadIdx.x & 31;
    int d = blockIdx.x * 8 + warp;
    if (d >= NN) return;
    int h = lane >> 2;
    int cnt = g_cnt[d];
    const int* bucket = g_csr + d * MAXDEG;
    float ald = g_ald1[d * HEADS + h];
    float4 acc = {0.f, 0.f, 0.f, 0.f};
    float den = 0.f;
    for (int i0 = 0; i0 < cnt; i0 += 32) {
        int i = i0 + lane;
        int s = (i < cnt) ? bucket[i] : 0;
        int lim = min(32, cnt - i0);
#pragma unroll 8
        for (int j = 0; j < lim; j++) {
            int sj = __shfl_sync(0xffffffffu, s, j);
            float al = g_als1[sj * HEADS + h] + ald;
            al = al > 0.f ? al : NEG_SLOPE * al;
            float w = __expf(al);
            den += w;
            uint2 hv = *(const uint2*)(g_h1h + sj * F1 + lane * 4);
            float2 f0 = __half22float2(*(const __half2*)&hv.x);
            float2 f1 = __half22float2(*(const __half2*)&hv.y);
            acc.x = fmaf(w, f0.x, acc.x);
            acc.y = fmaf(w, f0.y, acc.y);
            acc.z = fmaf(w, f1.x, acc.z);
            acc.w = fmaf(w, f1.y, acc.w);
        }
    }
    float inv = 1.f / den;
    float4 bv = *(const float4*)(b1 + lane * 4);
    float4 o;
    o.x = acc.x * inv + bv.x;
    o.y = acc.y * inv + bv.y;
    o.z = acc.z * inv + bv.z;
    o.w = acc.w * inv + bv.w;
    o.x = o.x > 0.f ? o.x : expm1f(o.x);
    o.y = o.y > 0.f ? o.y : expm1f(o.y);
    o.z = o.z > 0.f ? o.z : expm1f(o.z);
    o.w = o.w > 0.f ? o.w : expm1f(o.w);
    *(float4*)(g_out1 + d * F1 + lane * 4) = o;
}

// ---------------- layer 2: GEMM, 16 rows/block, smem-staged rows (R8 shape) ----------------
__global__ void k_gemm2(const float* __restrict__ W2,
                        const float* __restrict__ as2, const float* __restrict__ ad2) {
    int t = threadIdx.x;
    int rbase = blockIdx.x * 16;
    __shared__ float4 sh[16][32];
    __shared__ float ws[F1][OUTC];
    const float4* src = (const float4*)(g_out1 + rbase * F1);
    ((float4*)sh)[t]       = src[t];
    ((float4*)sh)[t + 256] = src[t + 256];
#pragma unroll
    for (int i = t; i < F1 * OUTC; i += 256) ws[i >> 4][i & 15] = W2[i];
    __syncthreads();
    int r_loc = t >> 4, c = t & 15;
    float acc = 0.f;
#pragma unroll 8
    for (int k4 = 0; k4 < 32; k4++) {
        float4 hv = sh[r_loc][k4];
        acc = fmaf(hv.x, ws[k4 * 4 + 0][c], acc);
        acc = fmaf(hv.y, ws[k4 * 4 + 1][c], acc);
        acc = fmaf(hv.z, ws[k4 * 4 + 2][c], acc);
        acc = fmaf(hv.w, ws[k4 * 4 + 3][c], acc);
    }
    int r = rbase + r_loc;
    g_h2h[r * OUTC + c] = __float2half(acc);
    float p = acc * as2[c], q = acc * ad2[c];
#pragma unroll
    for (int off = 8; off >= 1; off >>= 1) {
        p += __shfl_down_sync(0xffffffffu, p, off, 16);
        q += __shfl_down_sync(0xffffffffu, q, off, 16);
    }
    if (c == 0) { g_als2[r] = p; g_ald2[r] = q; }
}

// ---------------- layer 2: aggregation, 16-lane group per dst node (R8 shape) ----------------
__global__ void k_agg2(const float* __restrict__ b2, float* __restrict__ out) {
    int t = threadIdx.x;
    int d = blockIdx.x * 16 + (t >> 4);
    if (d >= NN) return;
    int c = t & 15;
    unsigned hm = 0xFFFFu << (t & 16);
    int cnt = g_cnt[d];
    const int* bucket = g_csr + d * MAXDEG;
    float ald = g_ald2[d];
    float acc = 0.f, den = 0.f;
    for (int i0 = 0; i0 < cnt; i0 += 16) {
        int i = i0 + c;
        int s = (i < cnt) ? bucket[i] : 0;
        int lim = min(16, cnt - i0);
#pragma unroll 8
        for (int j = 0; j < lim; j++) {
            int sj = __shfl_sync(hm, s, j, 16);
            float al = g_als2[sj] + ald;
            al = al > 0.f ? al : NEG_SLOPE * al;
            float w = __expf(al);
            den += w;
            acc = fmaf(w, __half2float(g_h2h[sj * OUTC + c]), acc);
        }
    }
    out[d * OUTC + c] = acc / den + b2[c];
}

// ---------------- launch ----------------
extern "C" void kernel_launch(void* const* d_in, const int* in_sizes, int n_in,
                              void* d_out, int out_size) {
    const float* x   = (const float*)d_in[0];
    const int*   ei  = (const int*)d_in[1];
    const float* W1  = (const float*)d_in[2];
    const float* as1 = (const float*)d_in[3];
    const float* ad1 = (const float*)d_in[4];
    const float* b1  = (const float*)d_in[5];
    const float* W2  = (const float*)d_in[6];
    const float* as2 = (const float*)d_in[7];
    const float* ad2 = (const float*)d_in[8];
    const float* b2  = (const float*)d_in[9];
    float* out = (float*)d_out;

    k_zero<<<(NN + 255) / 256, 256>>>();
    k_fill<<<(EE / 4 + 255) / 256, 256>>>(ei);
    k_convW<<<(F1 * F1 + 255) / 256, 256>>>(W1);
    k_gemm1<<<(NN + 31) / 32, 256>>>(x, as1, ad1);
    k_agg1<<<(NN + 7) / 8, 256>>>(b1);
    k_gemm2<<<(NN + 15) / 16, 256>>>(W2, as2, ad2);
    k_agg2<<<(NN + 15) / 16, 256>>>(b2, out);
}

// round 12
// speedup vs baseline: 1.4548x; 1.2476x over previous
#include <cuda_runtime.h>
#include <cuda_fp16.h>
#include <mma.h>
#include <math.h>

using namespace nvcuda;

#define NN 50000
#define EE 800000
#define F1 128
#define HEADS 8
#define HID 16
#define OUTC 16
#define NEG_SLOPE 0.2f
#define MAXDEG 64

#define LDA 136     // half, padded (272B row stride -> conflict-free ldsm)
#define LDB 136     // half, padded
#define LDC 132     // float, padded (528B row stride)
#define ROWS_PER_BLK 64
#define SMEM_B_BYTES (F1 * LDB * 2)                       // 34816
#define SMEM_AC_BYTES (ROWS_PER_BLK * LDC * 4)            // 33792 (>= A's 64*136*2)
#define SMEM_TOTAL (SMEM_B_BYTES + SMEM_AC_BYTES)         // 68608

// ---------------- scratch ----------------
__device__ __align__(16) __half g_h1h[NN * F1];
__device__ __align__(16) float  g_out1[NN * F1];
__device__ float g_als1[NN * HEADS];
__device__ float g_ald1[NN * HEADS];
__device__ __align__(16) __half g_h2h[NN * OUTC];
__device__ float g_als2[NN];
__device__ float g_ald2[NN];
__device__ int   g_cnt[NN];
__device__ int   g_csr[NN * MAXDEG];
__device__ __align__(16) __half g_W1h[F1 * F1];

// ---------------- bucket init: self loop in slot 0 ----------------
__global__ void k_zero() {
    int i = blockIdx.x * blockDim.x + threadIdx.x;
    if (i < NN) {
        g_cnt[i] = 1;
        g_csr[i * MAXDEG] = i;
    }
}

__global__ void k_fill(const int* __restrict__ ei) {
    int base = (blockIdx.x * blockDim.x + threadIdx.x) * 4;
    if (base >= EE) return;
#pragma unroll
    for (int k = 0; k < 4; k++) {
        int e = base + k;
        if (e < EE) {
            int s = ei[e], d = ei[EE + e];
            int pos = atomicAdd(&g_cnt[d], 1);
            if (pos < MAXDEG) g_csr[d * MAXDEG + pos] = s;
        }
    }
}

// ---------------- W1 -> half ----------------
__global__ void k_convW(const float* __restrict__ W1) {
    int i = blockIdx.x * blockDim.x + threadIdx.x;
    if (i < F1 * F1) g_W1h[i] = __float2half(W1[i]);
}

// ---------------- layer 1: wmma GEMM (64 rows/block, padded smem) + fused logits ----------------
__global__ void __launch_bounds__(256) k_gemm1(const float* __restrict__ x,
                                               const float* __restrict__ as1,
                                               const float* __restrict__ ad1) {
    extern __shared__ __align__(16) char dsm[];
    __half* Bs = (__half*)dsm;                    // [k][n] ld=LDB
    char* ACbuf = dsm + SMEM_B_BYTES;
    __half* As = (__half*)ACbuf;                  // [r][k] ld=LDA
    float*  Cs = (float*)ACbuf;                   // [r][n] ld=LDC (after mma)

    int t = threadIdx.x;
    int rows = blockIdx.x * ROWS_PER_BLK;

    // stage A: 64x128 fp32 -> half, padded rows; 2048 float4, 8 per thread
#pragma unroll
    for (int i = 0; i < 8; i++) {
        int idx = t + 256 * i;
        int le  = idx * 4;
        int r   = le >> 7;
        int c   = le & 127;
        float4 f = {0.f, 0.f, 0.f, 0.f};
        if (rows + r < NN) f = ((const float4*)x)[rows * 32 + idx];
        __half2* dst = (__half2*)(As + r * LDA + c);
        dst[0] = __floats2half2_rn(f.x, f.y);
        dst[1] = __floats2half2_rn(f.z, f.w);
    }
    // stage B: 128x128 half, padded rows; 2048 int4 (8 halves each), 8 per thread
#pragma unroll
    for (int i = 0; i < 8; i++) {
        int idx = t + 256 * i;
        int le  = idx * 8;
        int k   = le >> 7;
        int n   = le & 127;
        *(int4*)(Bs + k * LDB + n) = ((const int4*)g_W1h)[idx];
    }
    __syncthreads();

    // mma: 8 warps; warp w owns output cols [16w,16w+16), 4 row tiles
    int w = t >> 5;
    wmma::fragment<wmma::accumulator, 16, 16, 16, float> c0, c1, c2, c3;
    wmma::fill_fragment(c0, 0.f);
    wmma::fill_fragment(c1, 0.f);
    wmma::fill_fragment(c2, 0.f);
    wmma::fill_fragment(c3, 0.f);
#pragma unroll
    for (int k = 0; k < 8; k++) {
        wmma::fragment<wmma::matrix_a, 16, 16, 16, __half, wmma::row_major> a0, a1, a2, a3;
        wmma::fragment<wmma::matrix_b, 16, 16, 16, __half, wmma::row_major> b;
        wmma::load_matrix_sync(b, Bs + (k * 16) * LDB + w * 16, LDB);
        wmma::load_matrix_sync(a0, As + (0 * 16) * LDA + k * 16, LDA);
        wmma::load_matrix_sync(a1, As + (1 * 16) * LDA + k * 16, LDA);
        wmma::load_matrix_sync(a2, As + (2 * 16) * LDA + k * 16, LDA);
        wmma::load_matrix_sync(a3, As + (3 * 16) * LDA + k * 16, LDA);
        wmma::mma_sync(c0, a0, b, c0);
        wmma::mma_sync(c1, a1, b, c1);
        wmma::mma_sync(c2, a2, b, c2);
        wmma::mma_sync(c3, a3, b, c3);
    }
    __syncthreads();                      // all A reads done before C overwrites
    wmma::store_matrix_sync(Cs + (0 * 16) * LDC + w * 16, c0, LDC, wmma::mem_row_major);
    wmma::store_matrix_sync(Cs + (1 * 16) * LDC + w * 16, c1, LDC, wmma::mem_row_major);
    wmma::store_matrix_sync(Cs + (2 * 16) * LDC + w * 16, c2, LDC, wmma::mem_row_major);
    wmma::store_matrix_sync(Cs + (3 * 16) * LDC + w * 16, c3, LDC, wmma::mem_row_major);
    __syncthreads();

    // epilogue: h1h store + per-head logits
    int col = t & 127;
    int rhalf = t >> 7;                   // 0 or 1
    float as = as1[col], ad = ad1[col];
#pragma unroll
    for (int r = 0; r < 32; r++) {
        int row = r * 2 + rhalf;
        int grow = rows + row;
        float val = Cs[row * LDC + col];
        float p = val * as, q = val * ad;
#pragma unroll
        for (int off = 8; off >= 1; off >>= 1) {
            p += __shfl_down_sync(0xffffffffu, p, off, 16);
            q += __shfl_down_sync(0xffffffffu, q, off, 16);
        }
        if (grow < NN) {
            g_h1h[grow * F1 + col] = __float2half(val);
            if ((col & 15) == 0) {
                g_als1[grow * HEADS + (col >> 4)] = p;
                g_ald1[grow * HEADS + (col >> 4)] = q;
            }
        }
    }
}

// ---------------- layer 1: aggregation, one WARP per dst node ----------------
__global__ void k_agg1(const float* __restrict__ b1) {
    int warp = threadIdx.x >> 5;
    int lane = threadIdx.x & 31;
    int d = blockIdx.x * 8 + warp;
    if (d >= NN) return;
    int h = lane >> 2;
    int cnt = g_cnt[d];
    const int* bucket = g_csr + d * MAXDEG;
    float ald = g_ald1[d * HEADS + h];
    float4 acc = {0.f, 0.f, 0.f, 0.f};
    float den = 0.f;
    for (int i0 = 0; i0 < cnt; i0 += 32) {
        int i = i0 + lane;
        int s = (i < cnt) ? bucket[i] : 0;
        int lim = min(32, cnt - i0);
#pragma unroll 8
        for (int j = 0; j < lim; j++) {
            int sj = __shfl_sync(0xffffffffu, s, j);
            float al = g_als1[sj * HEADS + h] + ald;
            al = al > 0.f ? al : NEG_SLOPE * al;
            float w = __expf(al);
            den += w;
            uint2 hv = *(const uint2*)(g_h1h + sj * F1 + lane * 4);
            float2 f0 = __half22float2(*(const __half2*)&hv.x);
            float2 f1 = __half22float2(*(const __half2*)&hv.y);
            acc.x = fmaf(w, f0.x, acc.x);
            acc.y = fmaf(w, f0.y, acc.y);
            acc.z = fmaf(w, f1.x, acc.z);
            acc.w = fmaf(w, f1.y, acc.w);
        }
    }
    float inv = 1.f / den;
    float4 bv = *(const float4*)(b1 + lane * 4);
    float4 o;
    o.x = acc.x * inv + bv.x;
    o.y = acc.y * inv + bv.y;
    o.z = acc.z * inv + bv.z;
    o.w = acc.w * inv + bv.w;
    o.x = o.x > 0.f ? o.x : expm1f(o.x);
    o.y = o.y > 0.f ? o.y : expm1f(o.y);
    o.z = o.z > 0.f ? o.z : expm1f(o.z);
    o.w = o.w > 0.f ? o.w : expm1f(o.w);
    *(float4*)(g_out1 + d * F1 + lane * 4) = o;
}

// ---------------- layer 2: GEMM, 16 rows/block, smem-staged rows ----------------
__global__ void k_gemm2(const float* __restrict__ W2,
                        const float* __restrict__ as2, const float* __restrict__ ad2) {
    int t = threadIdx.x;
    int rbase = blockIdx.x * 16;
    __shared__ float4 sh[16][32];
    __shared__ float ws[F1][OUTC];
    const float4* src = (const float4*)(g_out1 + rbase * F1);
    ((float4*)sh)[t]       = src[t];
    ((float4*)sh)[t + 256] = src[t + 256];
#pragma unroll
    for (int i = t; i < F1 * OUTC; i += 256) ws[i >> 4][i & 15] = W2[i];
    __syncthreads();
    int r_loc = t >> 4, c = t & 15;
    float acc = 0.f;
#pragma unroll 8
    for (int k4 = 0; k4 < 32; k4++) {
        float4 hv = sh[r_loc][k4];
        acc = fmaf(hv.x, ws[k4 * 4 + 0][c], acc);
        acc = fmaf(hv.y, ws[k4 * 4 + 1][c], acc);
        acc = fmaf(hv.z, ws[k4 * 4 + 2][c], acc);
        acc = fmaf(hv.w, ws[k4 * 4 + 3][c], acc);
    }
    int r = rbase + r_loc;
    g_h2h[r * OUTC + c] = __float2half(acc);
    float p = acc * as2[c], q = acc * ad2[c];
#pragma unroll
    for (int off = 8; off >= 1; off >>= 1) {
        p += __shfl_down_sync(0xffffffffu, p, off, 16);
        q += __shfl_down_sync(0xffffffffu, q, off, 16);
    }
    if (c == 0) { g_als2[r] = p; g_ald2[r] = q; }
}

// ---------------- layer 2: aggregation, 16-lane group per dst node ----------------
__global__ void k_agg2(const float* __restrict__ b2, float* __restrict__ out) {
    int t = threadIdx.x;
    int d = blockIdx.x * 16 + (t >> 4);
    if (d >= NN) return;
    int c = t & 15;
    unsigned hm = 0xFFFFu << (t & 16);
    int cnt = g_cnt[d];
    const int* bucket = g_csr + d * MAXDEG;
    float ald = g_ald2[d];
    float acc = 0.f, den = 0.f;
    for (int i0 = 0; i0 < cnt; i0 += 16) {
        int i = i0 + c;
        int s = (i < cnt) ? bucket[i] : 0;
        int lim = min(16, cnt - i0);
#pragma unroll 8
        for (int j = 0; j < lim; j++) {
            int sj = __shfl_sync(hm, s, j, 16);
            float al = g_als2[sj] + ald;
            al = al > 0.f ? al : NEG_SLOPE * al;
            float w = __expf(al);
            den += w;
            acc = fmaf(w, __half2float(g_h2h[sj * OUTC + c]), acc);
        }
    }
    out[d * OUTC + c] = acc / den + b2[c];
}

// ---------------- launch ----------------
extern "C" void kernel_launch(void* const* d_in, const int* in_sizes, int n_in,
                              void* d_out, int out_size) {
    const float* x   = (const float*)d_in[0];
    const int*   ei  = (const int*)d_in[1];
    const float* W1  = (const float*)d_in[2];
    const float* as1 = (const float*)d_in[3];
    const float* ad1 = (const float*)d_in[4];
    const float* b1  = (const float*)d_in[5];
    const float* W2  = (const float*)d_in[6];
    const float* as2 = (const float*)d_in[7];
    const float* ad2 = (const float*)d_in[8];
    const float* b2  = (const float*)d_in[9];
    float* out = (float*)d_out;

    cudaFuncSetAttribute(k_gemm1, cudaFuncAttributeMaxDynamicSharedMemorySize, SMEM_TOTAL);

    k_zero<<<(NN + 255) / 256, 256>>>();
    k_fill<<<(EE / 4 + 255) / 256, 256>>>(ei);
    k_convW<<<(F1 * F1 + 255) / 256, 256>>>(W1);
    k_gemm1<<<(NN + ROWS_PER_BLK - 1) / ROWS_PER_BLK, 256, SMEM_TOTAL>>>(x, as1, ad1);
    k_agg1<<<(NN + 7) / 8, 256>>>(b1);
    k_gemm2<<<(NN + 15) / 16, 256>>>(W2, as2, ad2);
    k_agg2<<<(NN + 15) / 16, 256>>>(b2, out);
}